// round 10
// baseline (speedup 1.0000x reference)
#include <cuda_runtime.h>
#include <cuda_fp16.h>
#include <cuda_bf16.h>
#include <mma.h>

using namespace nvcuda;

// GCN 2-layer: x[N,128] -> GCNConv(128,64) -> relu -> GCNConv(64,32)
// gemm1: fp16 tensor cores (known-good R7). Aggregation: warp-per-node CSR
// gather (no divergence, 4-8 rows in flight per warp), fp16 operands.
// gemm2 fused into the layer-1 gather. CSR build overlapped with gemm1.

#define NN    100000
#define IN_F  128
#define H_F   64
#define OUT_F 32
#define CAP   64   // max in-degree; Binomial(1.6M, 1e-5): P(>=64) ~ 1e-26

// ---------------- scratch ----------------
__device__ int     g_cursor[NN];
__device__ int     g_adj[NN * CAP];          // src lists keyed by dst (rows 256B-aligned)
__device__ float   g_dinv[NN];
__device__ __align__(16) __half2 g_g1h[NN * (H_F / 2)];    // UNscaled x@W1^T, fp16       (12.8 MB)
__device__ __align__(16) __half2 g_g2h[NN * (OUT_F / 2)];  // dinv[v]*(relu_h@W2^T), fp16  (6.4 MB)

__device__ __forceinline__ void h8(uint4 u, float* f) {
    const __half2* h = (const __half2*)&u;
    float2 a0 = __half22float2(h[0]);
    float2 a1 = __half22float2(h[1]);
    float2 a2 = __half22float2(h[2]);
    float2 a3 = __half22float2(h[3]);
    f[0] = a0.x; f[1] = a0.y; f[2] = a1.x; f[3] = a1.y;
    f[4] = a2.x; f[5] = a2.y; f[6] = a3.x; f[7] = a3.y;
}

// ---------------- CSR build (side stream, overlaps gemm1) ----------------

__global__ void k_zero(int n) {
    int v = blockIdx.x * blockDim.x + threadIdx.x;
    if (v < n) g_cursor[v] = 0;
}

__global__ void k_fill(const int* __restrict__ src, const int* __restrict__ dst, int e) {
    int i = blockIdx.x * blockDim.x + threadIdx.x;
    if (i >= e) return;
    int d = dst[i];
    int s = src[i];
    int slot = atomicAdd(&g_cursor[d], 1);
    if (slot < CAP) g_adj[d * CAP + slot] = s;
}

__global__ void k_dinv(int n) {
    int v = blockIdx.x * blockDim.x + threadIdx.x;
    if (v < n) g_dinv[v] = rsqrtf((float)g_cursor[v] + 1.0f);
}

// ---------------- GEMM1 (fp16 tensor cores): g1[v] = x[v] @ W1^T, fp16 out ----------------
// (verbatim R7 known-good version)

#define G1_NODES 128
#define WS_LD 136
#define G1_SMEM (G1_NODES * 136 * 2 + H_F * WS_LD * 2)   // 52224 B

__global__ __launch_bounds__(256) void k_gemm1(const float* __restrict__ x,
                                               const float* __restrict__ W1,  // [64,128]
                                               int n) {
    extern __shared__ __align__(16) char dynbuf[];
    __half* xs = (__half*)dynbuf;                          // [128][136]
    float*  cs = (float*)dynbuf;                           // [128][68]
    __half* ws = (__half*)(dynbuf + G1_NODES * 136 * 2);   // [64][136]

    const int tid = threadIdx.x;
    const int nb = blockIdx.x * G1_NODES;

    {
        const float4* xv = (const float4*)x;
        __half2* xsh2 = (__half2*)xs;     // row stride 68 half2
        for (int i = tid; i < G1_NODES * 32; i += 256) {
            int row = i >> 5, q = i & 31;
            int node = nb + row;
            float4 v = (node < n) ? xv[(size_t)node * 32 + q] : make_float4(0, 0, 0, 0);
            xsh2[row * 68 + 2 * q]     = __floats2half2_rn(v.x, v.y);
            xsh2[row * 68 + 2 * q + 1] = __floats2half2_rn(v.z, v.w);
        }
    }
    for (int i = tid; i < H_F * IN_F; i += 256) {
        int h = i >> 7, k = i & 127;
        ws[h * WS_LD + k] = __float2half(W1[i]);
    }
    __syncthreads();

    const int w = tid >> 5;

    wmma::fragment<wmma::accumulator, 16, 16, 16, float> acc[4];
    #pragma unroll
    for (int f = 0; f < 4; f++) wmma::fill_fragment(acc[f], 0.0f);

    #pragma unroll
    for (int k = 0; k < IN_F / 16; k++) {
        wmma::fragment<wmma::matrix_a, 16, 16, 16, __half, wmma::row_major> a;
        wmma::load_matrix_sync(a, &xs[(w * 16) * 136 + k * 16], 136);
        #pragma unroll
        for (int f = 0; f < 4; f++) {
            wmma::fragment<wmma::matrix_b, 16, 16, 16, __half, wmma::col_major> b;
            wmma::load_matrix_sync(b, &ws[(f * 16) * WS_LD + k * 16], WS_LD);
            wmma::mma_sync(acc[f], a, b, acc[f]);
        }
    }

    __syncthreads();
    #pragma unroll
    for (int f = 0; f < 4; f++)
        wmma::store_matrix_sync(&cs[(w * 16) * 68 + f * 16], acc[f], 68, wmma::mem_row_major);
    __syncthreads();

    for (int i = tid; i < G1_NODES * 32; i += 256) {
        int row = i >> 5, p = i & 31;
        int node = nb + row;
        if (node < n)
            g_g1h[node * 32 + p] =
                __floats2half2_rn(cs[row * 68 + 2 * p], cs[row * 68 + 2 * p + 1]);
    }
}

// ---------------- fused agg1 + gemm2, warp-per-node ----------------
// 256 threads = 8 warps = 8 nodes/block. Within a warp: 4 neighbor-groups x
// 8 row-lanes; group grp walks neighbors j = grp, grp+4, ... (uniform cnt, no
// divergence), 2x unrolled -> 8 row gathers in flight per warp. Partials
// combined via shfl_xor(8),(16). Then relu(dinv*agg+b1) -> hs[8][68]; gemm2:
// one output per lane (W2s rows conflict-free at 68-float stride).

__global__ __launch_bounds__(256) void k_agg1g2(const float* __restrict__ b1,
                                                const float* __restrict__ W2,  // [32,64]
                                                int n) {
    __shared__ float W2s[OUT_F * 68];   // 8704 B
    __shared__ float bs[H_F];
    __shared__ float hs[8 * 68];        // 2176 B

    const int tid = threadIdx.x;
    for (int i = tid; i < OUT_F * H_F; i += 256) {
        int o = i >> 6, k = i & 63;
        W2s[o * 68 + k] = W2[i];
    }
    for (int i = tid; i < H_F; i += 256) bs[i] = b1[i];
    __syncthreads();

    const int warp = tid >> 5;
    const int lane = tid & 31;
    const int grp  = lane >> 3;          // 0..3
    const int c    = lane & 7;           // 0..7 (16B column of the 128B row)
    const int v    = blockIdx.x * 8 + warp;
    const bool valid = (v < n);

    float dv = 0.0f;
    float acc[8];
    #pragma unroll
    for (int i = 0; i < 8; i++) acc[i] = 0.0f;

    if (valid) {
        int cnt = g_cursor[v];
        if (cnt > CAP) cnt = CAP;
        dv = g_dinv[v];
        const uint4* rows = (const uint4*)g_g1h;   // 8 uint4 per 128B node row

        if (grp == 0) {                 // self-loop term on group 0
            float f[8];
            h8(rows[v * 8 + c], f);
            #pragma unroll
            for (int i = 0; i < 8; i++) acc[i] = dv * f[i];
        }

        const int* adj = &g_adj[v * CAP];
        int j = grp;
        // 2x unrolled: two neighbors per group in flight -> 8 rows/warp
        for (; j + 4 < cnt; j += 8) {
            int s0 = adj[j];
            int s1 = adj[j + 4];
            uint4 u0 = rows[s0 * 8 + c];
            uint4 u1 = rows[s1 * 8 + c];
            float d0 = g_dinv[s0];
            float d1 = g_dinv[s1];
            float ft[8];
            h8(u0, ft);
            #pragma unroll
            for (int i = 0; i < 8; i++) acc[i] = fmaf(d0, ft[i], acc[i]);
            h8(u1, ft);
            #pragma unroll
            for (int i = 0; i < 8; i++) acc[i] = fmaf(d1, ft[i], acc[i]);
        }
        if (j < cnt) {
            int s = adj[j];
            uint4 u = rows[s * 8 + c];
            float ds = g_dinv[s];
            float ft[8];
            h8(u, ft);
            #pragma unroll
            for (int i = 0; i < 8; i++) acc[i] = fmaf(ds, ft[i], acc[i]);
        }
    }

    // combine the 4 neighbor-groups (lanes with equal c)
    #pragma unroll
    for (int i = 0; i < 8; i++) {
        acc[i] += __shfl_xor_sync(0xffffffffu, acc[i], 8);
        acc[i] += __shfl_xor_sync(0xffffffffu, acc[i], 16);
    }

    if (grp == 0) {
        float* hrow = &hs[warp * 68 + 8 * c];
        #pragma unroll
        for (int i = 0; i < 8; i++)
            hrow[i] = valid ? fmaxf(acc[i] * dv + bs[8 * c + i], 0.0f) : 0.0f;
    }
    __syncthreads();

    // gemm2: lane o computes out[o] = dinv * dot(hs[warp], W2s[o])
    float val = 0.0f;
    {
        const float4* hrow = (const float4*)&hs[warp * 68];      // broadcast reads
        const float4* wrow = (const float4*)&W2s[lane * 68];     // conflict-free
        #pragma unroll 4
        for (int k4 = 0; k4 < 16; k4++) {
            float4 h4 = hrow[k4];
            float4 w4 = wrow[k4];
            val += h4.x * w4.x + h4.y * w4.y + h4.z * w4.z + h4.w * w4.w;
        }
    }
    val *= dv;
    float vhi = __shfl_down_sync(0xffffffffu, val, 1);
    if (valid && (lane & 1) == 0)
        g_g2h[v * 16 + (lane >> 1)] = __floats2half2_rn(val, vhi);
}

// ---------------- agg2 + epilogue, warp-per-node ----------------
// 8 neighbor-groups x 4 row-lanes (64B rows). j = grp, grp+8, ...
// Reduce via shfl_xor(4),(8),(16). Group 0's 4 lanes write the output.

__global__ __launch_bounds__(256) void k_agg2(float* __restrict__ out,
                                              const float* __restrict__ b2, int n) {
    const int tid = threadIdx.x;
    const int warp = tid >> 5;
    const int lane = tid & 31;
    const int grp  = lane >> 2;          // 0..7
    const int c    = lane & 3;           // 0..3 (16B column of the 64B row)
    const int v    = blockIdx.x * 8 + warp;
    const bool valid = (v < n);

    float acc[8];
    #pragma unroll
    for (int i = 0; i < 8; i++) acc[i] = 0.0f;

    if (valid) {
        int cnt = g_cursor[v];
        if (cnt > CAP) cnt = CAP;
        const uint4* rows = (const uint4*)g_g2h;   // 4 uint4 per 64B node row

        if (grp == 0) h8(rows[v * 4 + c], acc);    // self-loop (pre-scaled)

        const int* adj = &g_adj[v * CAP];
        int j = grp;
        for (; j + 8 < cnt; j += 16) {             // 2x unroll -> 16 rows/warp in flight
            int s0 = adj[j];
            int s1 = adj[j + 8];
            uint4 u0 = rows[s0 * 4 + c];
            uint4 u1 = rows[s1 * 4 + c];
            float ft[8];
            h8(u0, ft);
            #pragma unroll
            for (int i = 0; i < 8; i++) acc[i] += ft[i];
            h8(u1, ft);
            #pragma unroll
            for (int i = 0; i < 8; i++) acc[i] += ft[i];
        }
        if (j < cnt) {
            uint4 u = rows[adj[j] * 4 + c];
            float ft[8];
            h8(u, ft);
            #pragma unroll
            for (int i = 0; i < 8; i++) acc[i] += ft[i];
        }
    }

    #pragma unroll
    for (int i = 0; i < 8; i++) {
        acc[i] += __shfl_xor_sync(0xffffffffu, acc[i], 4);
        acc[i] += __shfl_xor_sync(0xffffffffu, acc[i], 8);
        acc[i] += __shfl_xor_sync(0xffffffffu, acc[i], 16);
    }

    if (valid && grp == 0) {
        float dvv = g_dinv[v];
        float4 ba = ((const float4*)b2)[2 * c];
        float4 bb = ((const float4*)b2)[2 * c + 1];
        float4* ov = (float4*)out;
        ov[v * 8 + 2 * c]     = make_float4(acc[0] * dvv + ba.x, acc[1] * dvv + ba.y,
                                            acc[2] * dvv + ba.z, acc[3] * dvv + ba.w);
        ov[v * 8 + 2 * c + 1] = make_float4(acc[4] * dvv + bb.x, acc[5] * dvv + bb.y,
                                            acc[6] * dvv + bb.z, acc[7] * dvv + bb.w);
    }
}

extern "C" void kernel_launch(void* const* d_in, const int* in_sizes, int n_in,
                              void* d_out, int out_size) {
    const float* x  = (const float*)d_in[0];
    const int*   ei = (const int*)d_in[1];
    const float* W1 = (const float*)d_in[2];
    const float* b1 = (const float*)d_in[3];
    const float* W2 = (const float*)d_in[4];
    const float* b2 = (const float*)d_in[5];
    float* out = (float*)d_out;

    const int n = in_sizes[0] / IN_F;     // 100000
    const int e = in_sizes[1] / 2;        // 1600000
    const int* src = ei;
    const int* dst = ei + e;

    // one-time host-side setup (no device allocation)
    static cudaStream_t side = nullptr;
    static cudaEvent_t e0 = nullptr, e1 = nullptr;
    if (!side) {
        cudaStreamCreateWithFlags(&side, cudaStreamNonBlocking);
        cudaEventCreateWithFlags(&e0, cudaEventDisableTiming);
        cudaEventCreateWithFlags(&e1, cudaEventDisableTiming);
        cudaFuncSetAttribute(k_gemm1, cudaFuncAttributeMaxDynamicSharedMemorySize, G1_SMEM);
    }

    const int T = 256;

    // fork: CSR build on side stream; gemm1 (independent) on main
    cudaEventRecord(e0, 0);
    cudaStreamWaitEvent(side, e0, 0);
    k_zero<<<(n + T - 1) / T, T, 0, side>>>(n);
    k_fill<<<(e + T - 1) / T, T, 0, side>>>(src, dst, e);
    k_dinv<<<(n + T - 1) / T, T, 0, side>>>(n);
    cudaEventRecord(e1, side);

    k_gemm1<<<(n + G1_NODES - 1) / G1_NODES, T, G1_SMEM>>>(x, W1, n);

    // join, then dependent chain (8 nodes per 256-thread block)
    cudaStreamWaitEvent(0, e1, 0);
    k_agg1g2<<<(n + 7) / 8, T>>>(b1, W2, n);
    k_agg2<<<(n + 7) / 8, T>>>(out, b2, n);
}

// round 11
// speedup vs baseline: 1.3323x; 1.3323x over previous
#include <cuda_runtime.h>
#include <cuda_fp16.h>
#include <cuda_bf16.h>
#include <mma.h>

using namespace nvcuda;

// GCN 2-layer: x[N,128] -> GCNConv(128,64) -> relu -> GCNConv(64,32)
// gemm1: fp16 tensor cores, 64 nodes/block @ 256 threads (75% occ).
// agg1+gemm2 fused, barrier-free hot path (quarter-warp per node).
// agg2: R7 4-lane/node gather. CSR build overlapped with gemm1.

#define NN    100000
#define IN_F  128
#define H_F   64
#define OUT_F 32
#define CAP   64   // max in-degree; Binomial(1.6M, 1e-5): P(>=64) ~ 1e-26

// ---------------- scratch ----------------
__device__ int     g_cursor[NN];
__device__ int     g_adj[NN * CAP];          // src lists keyed by dst (rows 256B-aligned)
__device__ float   g_dinv[NN];
__device__ __align__(16) __half2 g_g1h[NN * (H_F / 2)];    // UNscaled x@W1^T, fp16       (12.8 MB)
__device__ __align__(16) __half2 g_g2h[NN * (OUT_F / 2)];  // dinv[v]*(relu_h@W2^T), fp16  (6.4 MB)

__device__ __forceinline__ void h8(uint4 u, float* f) {
    const __half2* h = (const __half2*)&u;
    float2 a0 = __half22float2(h[0]);
    float2 a1 = __half22float2(h[1]);
    float2 a2 = __half22float2(h[2]);
    float2 a3 = __half22float2(h[3]);
    f[0] = a0.x; f[1] = a0.y; f[2] = a1.x; f[3] = a1.y;
    f[4] = a2.x; f[5] = a2.y; f[6] = a3.x; f[7] = a3.y;
}

// ---------------- CSR build (side stream, overlaps gemm1) ----------------

__global__ void k_zero(int n) {
    int v = blockIdx.x * blockDim.x + threadIdx.x;
    if (v < n) g_cursor[v] = 0;
}

__global__ void k_fill(const int* __restrict__ src, const int* __restrict__ dst, int e) {
    int i = blockIdx.x * blockDim.x + threadIdx.x;
    if (i >= e) return;
    int d = dst[i];
    int s = src[i];
    int slot = atomicAdd(&g_cursor[d], 1);
    if (slot < CAP) g_adj[d * CAP + slot] = s;
}

__global__ void k_dinv(int n) {
    int v = blockIdx.x * blockDim.x + threadIdx.x;
    if (v < n) g_dinv[v] = rsqrtf((float)g_cursor[v] + 1.0f);
}

// ---------------- GEMM1 (fp16 tensor cores): g1[v] = x[v] @ W1^T, fp16 out ----------------
// 256 threads = 8 warps; 64 nodes/block. Warp w: row-tile rt = w>>1 (rows
// rt*16..+15), f-half = w&1 (output col tiles 2*half, 2*half+1).
// xs [64][136] half; ws [64][136] half (col-major B view); cs [64][68] fp32
// unions with xs. All strides 272 B (16B-aligned for LDSM).

#define G1_NODES 64
#define WS_LD 136
#define G1_SMEM (G1_NODES * 136 * 2 + H_F * WS_LD * 2)   // 34816 B

__global__ __launch_bounds__(256) void k_gemm1(const float* __restrict__ x,
                                               const float* __restrict__ W1,  // [64,128]
                                               int n) {
    extern __shared__ __align__(16) char dynbuf[];
    __half* xs = (__half*)dynbuf;                          // [64][136]
    float*  cs = (float*)dynbuf;                           // [64][68]
    __half* ws = (__half*)(dynbuf + G1_NODES * 136 * 2);   // [64][136]

    const int tid = threadIdx.x;
    const int nb = blockIdx.x * G1_NODES;

    // load + convert x tile
    {
        const float4* xv = (const float4*)x;
        __half2* xsh2 = (__half2*)xs;     // row stride 68 half2
        for (int i = tid; i < G1_NODES * 32; i += 256) {
            int row = i >> 5, q = i & 31;
            int node = nb + row;
            float4 v = (node < n) ? xv[(size_t)node * 32 + q] : make_float4(0, 0, 0, 0);
            xsh2[row * 68 + 2 * q]     = __floats2half2_rn(v.x, v.y);
            xsh2[row * 68 + 2 * q + 1] = __floats2half2_rn(v.z, v.w);
        }
    }
    // load + convert W1
    for (int i = tid; i < H_F * IN_F; i += 256) {
        int h = i >> 7, k = i & 127;
        ws[h * WS_LD + k] = __float2half(W1[i]);
    }
    __syncthreads();

    const int w = tid >> 5;
    const int rt = w >> 1;       // row tile 0..3
    const int half = w & 1;      // output-column half 0..1

    wmma::fragment<wmma::accumulator, 16, 16, 16, float> acc[2];
    #pragma unroll
    for (int f = 0; f < 2; f++) wmma::fill_fragment(acc[f], 0.0f);

    #pragma unroll
    for (int k = 0; k < IN_F / 16; k++) {
        wmma::fragment<wmma::matrix_a, 16, 16, 16, __half, wmma::row_major> a;
        wmma::load_matrix_sync(a, &xs[(rt * 16) * 136 + k * 16], 136);
        #pragma unroll
        for (int f = 0; f < 2; f++) {
            wmma::fragment<wmma::matrix_b, 16, 16, 16, __half, wmma::col_major> b;
            wmma::load_matrix_sync(b, &ws[((half * 2 + f) * 16) * WS_LD + k * 16], WS_LD);
            wmma::mma_sync(acc[f], a, b, acc[f]);
        }
    }

    __syncthreads();   // xs reads done; cs overwrites the same memory
    #pragma unroll
    for (int f = 0; f < 2; f++)
        wmma::store_matrix_sync(&cs[(rt * 16) * 68 + (half * 2 + f) * 16], acc[f],
                                68, wmma::mem_row_major);
    __syncthreads();

    // convert fp32 stage -> fp16 global
    for (int i = tid; i < G1_NODES * 32; i += 256) {
        int row = i >> 5, p = i & 31;
        int node = nb + row;
        if (node < n)
            g_g1h[node * 32 + p] =
                __floats2half2_rn(cs[row * 68 + 2 * p], cs[row * 68 + 2 * p + 1]);
    }
}

// ---------------- fused agg1 + gemm2, barrier-free hot path ----------------
// 256 threads = 32 nodes x 8 lanes (quarter-warp per node). Gather (R7 4-wide
// unroll) -> hs[g] (written/read only by node g's own 8 lanes, __syncwarp) ->
// per-lane gemm2 outputs o = c + 8j (W2s reads conflict-free at 68-float
// stride) -> fp16 pairs via shfl_down(1), stored by even lanes.

__global__ __launch_bounds__(256) void k_agg1g2(const float* __restrict__ b1,
                                                const float* __restrict__ W2,  // [32,64]
                                                int n) {
    __shared__ float W2s[OUT_F * 68];   // 8704 B
    __shared__ float bs[H_F];
    __shared__ float hs[32 * 68];       // 8704 B

    const int tid = threadIdx.x;
    for (int i = tid; i < OUT_F * H_F; i += 256) {
        int o = i >> 6, k = i & 63;
        W2s[o * 68 + k] = W2[i];
    }
    for (int i = tid; i < H_F; i += 256) bs[i] = b1[i];
    __syncthreads();   // only barrier: W2s/bs visible to all

    const int g = tid >> 3;
    const int c = tid & 7;
    const int v = blockIdx.x * 32 + g;
    const bool valid = (v < n);

    float dv = 0.0f;
    float acc[8];
    #pragma unroll
    for (int i = 0; i < 8; i++) acc[i] = 0.0f;

    if (valid) {
        int cnt = g_cursor[v];
        if (cnt > CAP) cnt = CAP;
        dv = g_dinv[v];
        const uint4* rows = (const uint4*)g_g1h;   // 8 uint4 per 128B node row

        float f[8];
        h8(rows[v * 8 + c], f);
        #pragma unroll
        for (int i = 0; i < 8; i++) acc[i] = dv * f[i];

        const int* adj = &g_adj[v * CAP];
        int j = 0;
        for (; j + 4 <= cnt; j += 4) {
            int4 sa = *(const int4*)&adj[j];       // 16B-aligned
            float d0 = g_dinv[sa.x], d1 = g_dinv[sa.y];
            float d2 = g_dinv[sa.z], d3 = g_dinv[sa.w];
            uint4 u0 = rows[sa.x * 8 + c];
            uint4 u1 = rows[sa.y * 8 + c];
            uint4 u2 = rows[sa.z * 8 + c];
            uint4 u3 = rows[sa.w * 8 + c];
            float ft[8];
            h8(u0, ft);
            #pragma unroll
            for (int i = 0; i < 8; i++) acc[i] = fmaf(d0, ft[i], acc[i]);
            h8(u1, ft);
            #pragma unroll
            for (int i = 0; i < 8; i++) acc[i] = fmaf(d1, ft[i], acc[i]);
            h8(u2, ft);
            #pragma unroll
            for (int i = 0; i < 8; i++) acc[i] = fmaf(d2, ft[i], acc[i]);
            h8(u3, ft);
            #pragma unroll
            for (int i = 0; i < 8; i++) acc[i] = fmaf(d3, ft[i], acc[i]);
        }
        for (; j < cnt; j++) {
            int s = adj[j];
            float ds = g_dinv[s];
            float ft[8];
            h8(rows[s * 8 + c], ft);
            #pragma unroll
            for (int i = 0; i < 8; i++) acc[i] = fmaf(ds, ft[i], acc[i]);
        }

        // relu(dinv*agg + b1) -> hs row (only this quarter-warp touches it)
        float* hrow = &hs[g * 68 + 8 * c];
        #pragma unroll
        for (int i = 0; i < 8; i++)
            hrow[i] = fmaxf(acc[i] * dv + bs[8 * c + i], 0.0f);
    }
    __syncwarp();      // hs row visibility within the warp

    // gemm2: lane computes outputs o = c + 8j from its node's hs row
    float oacc[4];
    #pragma unroll
    for (int j = 0; j < 4; j++) oacc[j] = 0.0f;
    {
        const float4* hrow = (const float4*)&hs[g * 68];         // broadcast in group
        #pragma unroll 4
        for (int k4 = 0; k4 < 16; k4++) {
            float4 h4 = hrow[k4];
            #pragma unroll
            for (int j = 0; j < 4; j++) {
                const float4 w4 = *(const float4*)&W2s[(c + 8 * j) * 68 + k4 * 4];
                oacc[j] += h4.x * w4.x + h4.y * w4.y + h4.z * w4.z + h4.w * w4.w;
            }
        }
    }
    // pair (o, o+1) = (even lane, odd lane) for each j; even lanes store fp16x2
    #pragma unroll
    for (int j = 0; j < 4; j++) {
        float lo = oacc[j] * dv;
        float hi = __shfl_down_sync(0xffffffffu, lo, 1);
        if (valid && (c & 1) == 0)
            g_g2h[v * 16 + (c >> 1) + 4 * j] = __floats2half2_rn(lo, hi);
    }
}

// ---------------- agg2 + epilogue: out[v] = dinv[v]*(g2[v] + sum g2[s]) + b2 ----------------
// 4 threads per node; lane c owns 16B = dims 8c..8c+7. g2 pre-scaled by dinv[src].

__global__ __launch_bounds__(256) void k_agg2(float* __restrict__ out,
                                              const float* __restrict__ b2, int n) {
    int gidx = blockIdx.x * blockDim.x + threadIdx.x;
    int v = gidx >> 2;
    int c = gidx & 3;
    if (v >= n) return;
    int cnt = g_cursor[v];
    if (cnt > CAP) cnt = CAP;
    const uint4* rows = (const uint4*)g_g2h;   // 4 uint4 per 64B node row

    float acc[8];
    h8(rows[v * 4 + c], acc);                  // self-loop (pre-scaled)

    const int* adj = &g_adj[v * CAP];
    int j = 0;
    for (; j + 4 <= cnt; j += 4) {
        int4 sa = *(const int4*)&adj[j];
        uint4 u0 = rows[sa.x * 4 + c];
        uint4 u1 = rows[sa.y * 4 + c];
        uint4 u2 = rows[sa.z * 4 + c];
        uint4 u3 = rows[sa.w * 4 + c];
        float ft[8];
        h8(u0, ft);
        #pragma unroll
        for (int i = 0; i < 8; i++) acc[i] += ft[i];
        h8(u1, ft);
        #pragma unroll
        for (int i = 0; i < 8; i++) acc[i] += ft[i];
        h8(u2, ft);
        #pragma unroll
        for (int i = 0; i < 8; i++) acc[i] += ft[i];
        h8(u3, ft);
        #pragma unroll
        for (int i = 0; i < 8; i++) acc[i] += ft[i];
    }
    for (; j < cnt; j++) {
        float ft[8];
        h8(rows[adj[j] * 4 + c], ft);
        #pragma unroll
        for (int i = 0; i < 8; i++) acc[i] += ft[i];
    }

    float dvv = g_dinv[v];
    float4 ba = ((const float4*)b2)[2 * c];
    float4 bb = ((const float4*)b2)[2 * c + 1];
    float4* ov = (float4*)out;
    ov[v * 8 + 2 * c]     = make_float4(acc[0] * dvv + ba.x, acc[1] * dvv + ba.y,
                                        acc[2] * dvv + ba.z, acc[3] * dvv + ba.w);
    ov[v * 8 + 2 * c + 1] = make_float4(acc[4] * dvv + bb.x, acc[5] * dvv + bb.y,
                                        acc[6] * dvv + bb.z, acc[7] * dvv + bb.w);
}

extern "C" void kernel_launch(void* const* d_in, const int* in_sizes, int n_in,
                              void* d_out, int out_size) {
    const float* x  = (const float*)d_in[0];
    const int*   ei = (const int*)d_in[1];
    const float* W1 = (const float*)d_in[2];
    const float* b1 = (const float*)d_in[3];
    const float* W2 = (const float*)d_in[4];
    const float* b2 = (const float*)d_in[5];
    float* out = (float*)d_out;

    const int n = in_sizes[0] / IN_F;     // 100000
    const int e = in_sizes[1] / 2;        // 1600000
    const int* src = ei;
    const int* dst = ei + e;

    // one-time host-side setup (no device allocation)
    static cudaStream_t side = nullptr;
    static cudaEvent_t e0 = nullptr, e1 = nullptr;
    if (!side) {
        cudaStreamCreateWithFlags(&side, cudaStreamNonBlocking);
        cudaEventCreateWithFlags(&e0, cudaEventDisableTiming);
        cudaEventCreateWithFlags(&e1, cudaEventDisableTiming);
        cudaFuncSetAttribute(k_gemm1, cudaFuncAttributeMaxDynamicSharedMemorySize, G1_SMEM);
    }

    const int T = 256;

    // fork: CSR build on side stream; gemm1 (independent) on main
    cudaEventRecord(e0, 0);
    cudaStreamWaitEvent(side, e0, 0);
    k_zero<<<(n + T - 1) / T, T, 0, side>>>(n);
    k_fill<<<(e + T - 1) / T, T, 0, side>>>(src, dst, e);
    k_dinv<<<(n + T - 1) / T, T, 0, side>>>(n);
    cudaEventRecord(e1, side);

    k_gemm1<<<(n + G1_NODES - 1) / G1_NODES, T, G1_SMEM>>>(x, W1, n);

    // join, then dependent chain
    cudaStreamWaitEvent(0, e1, 0);
    k_agg1g2<<<(n + 31) / 32, T>>>(b1, W2, n);
    k_agg2<<<(n * 4 + T - 1) / T, T>>>(out, b2, n);
}